// round 14
// baseline (speedup 1.0000x reference)
#include <cuda_runtime.h>
#include <cuda_fp16.h>
#include <cstdint>

// ---------------- problem dims ----------------
#define Bb 64
#define Nn 1024
#define Din 16
#define Dd 256
#define Hh 4
#define DH 64
#define Ll 3
#define DFF 1024
#define Kk 64
#define MM (Bb*Nn)          // 65536 rows

// ---------------- scratch (static device memory) ----------------
__device__ __half g_h[MM*Dd];           // 32 MB hidden state (fp16)
__device__ __half g_scr[MM*DFF];        // 128 MB qkv|ao or ffn hidden
__device__ uint32_t g_wpk[1212416];     // packed fp16 weights (u64-fragment layout)
__device__ float g_hmean[Bb*Dd];
__device__ float g_qv[Bb*Dd];
__device__ float g_t1[Bb*Dd];
__device__ float g_logits[Bb*Nn];
__device__ float g_scores[Bb*Nn];

// packed-weight offsets (uint32 units)
#define OFF_QKV  0            // 3 x [64 u64-rows][768]
#define OFF_WO   294912       // 3 x [64][256]
#define OFF_W1   393216       // 3 x [64][1024]
#define OFF_W2   786432       // 3 x [256][256]
#define OFF_SHA  1179648      // [64][256]

__device__ __forceinline__ uint32_t pkhf(float lo, float hi) {
    uint32_t r;
    asm("cvt.rn.f16x2.f32 %0, %1, %2;" : "=r"(r) : "f"(hi), "f"(lo));
    return r;
}

__device__ __forceinline__ void mma_f16(float* c, const uint32_t* a, const uint32_t* b) {
    asm volatile(
        "mma.sync.aligned.m16n8k16.row.col.f32.f16.f16.f32 "
        "{%0,%1,%2,%3}, {%4,%5,%6,%7}, {%8,%9}, {%0,%1,%2,%3};"
        : "+f"(c[0]), "+f"(c[1]), "+f"(c[2]), "+f"(c[3])
        : "r"(a[0]), "r"(a[1]), "r"(a[2]), "r"(a[3]), "r"(b[0]), "r"(b[1]));
}

__device__ __forceinline__ void ldmx4(uint32_t* r, uint32_t saddr) {
    asm volatile("ldmatrix.sync.aligned.m8n8.x4.shared.b16 {%0,%1,%2,%3}, [%4];"
        : "=r"(r[0]), "=r"(r[1]), "=r"(r[2]), "=r"(r[3]) : "r"(saddr));
}

__device__ __forceinline__ void cp16(void* smem, const void* gmem) {
    uint32_t s = (uint32_t)__cvta_generic_to_shared(smem);
    asm volatile("cp.async.cg.shared.global [%0], [%1], 16;" :: "r"(s), "l"(gmem));
}
#define CP_COMMIT() asm volatile("cp.async.commit_group;")
#define CP_WAIT(n)  asm volatile("cp.async.wait_group %0;" :: "n"(n))

// ---------------- fused weight pack: all 7 weights in one launch ----------------
__global__ void packall_kernel(const float* __restrict__ Wq, const float* __restrict__ Wk,
                               const float* __restrict__ Wv, const float* __restrict__ Wo,
                               const float* __restrict__ W1, const float* __restrict__ W2,
                               const float* __restrict__ sha, uint32_t* __restrict__ dst)
{
    int seg = blockIdx.y;
    int i = blockIdx.x*256 + threadIdx.x;
    const float* src; int Nsrc, NdT, colOff, KN, KNh, lds, total, dstOff;
    switch (seg) {
        case 0: src=Wq;  dstOff=OFF_QKV; Nsrc=256;  NdT=768;  colOff=0;   KN=65536;  KNh=32768;  lds=98304;  total=98304;  break;
        case 1: src=Wk;  dstOff=OFF_QKV; Nsrc=256;  NdT=768;  colOff=256; KN=65536;  KNh=32768;  lds=98304;  total=98304;  break;
        case 2: src=Wv;  dstOff=OFF_QKV; Nsrc=256;  NdT=768;  colOff=512; KN=65536;  KNh=32768;  lds=98304;  total=98304;  break;
        case 3: src=Wo;  dstOff=OFF_WO;  Nsrc=256;  NdT=256;  colOff=0;   KN=65536;  KNh=32768;  lds=32768;  total=98304;  break;
        case 4: src=W1;  dstOff=OFF_W1;  Nsrc=1024; NdT=1024; colOff=0;   KN=262144; KNh=131072; lds=131072; total=393216; break;
        case 5: src=W2;  dstOff=OFF_W2;  Nsrc=256;  NdT=256;  colOff=0;   KN=262144; KNh=131072; lds=131072; total=393216; break;
        default:src=sha; dstOff=OFF_SHA; Nsrc=256;  NdT=256;  colOff=0;   KN=65536;  KNh=32768;  lds=32768;  total=32768;  break;
    }
    if (i >= total) return;
    int l = i / KNh;
    int rem = i - l*KNh;
    int kp = rem / Nsrc, n = rem - kp*Nsrc;
    int t = kp >> 4, r = kp & 15;
    int j = ((r >> 3) << 2) | (r & 3);
    int half = (r >> 2) & 1;
    const float* s = src + (size_t)l*KN;
    dst[(size_t)dstOff + (size_t)l*lds
        + ((size_t)(t*8 + j)*NdT + colOff + n)*2 + half] =
        pkhf(s[(size_t)(2*kp)*Nsrc + n], s[(size_t)(2*kp+1)*Nsrc + n]);
}

// ---------------- zero hmean ----------------
__global__ void zeroh_kernel(float* __restrict__ p)
{
    p[blockIdx.x*256 + threadIdx.x] = 0.f;
}

// ---------------- embedding: 16 rows/block, W staged in smem ----------------
__global__ void embed_kernel(const float* __restrict__ x, const float* __restrict__ W,
                             const float* __restrict__ bb, __half* __restrict__ h)
{
    __shared__ float Ws[Din*Dd];
    __shared__ float xs[16*Din];
    __shared__ float bsm[Dd];
    const int tid = threadIdx.x;
    const int m0 = blockIdx.x*16;
#pragma unroll
    for (int i = tid; i < Din*Dd; i += 256) Ws[i] = W[i];
    xs[tid] = x[m0*Din + tid];
    bsm[tid] = bb[tid];
    __syncthreads();
    const int d = tid;
#pragma unroll
    for (int r = 0; r < 16; r++) {
        float a = bsm[d];
#pragma unroll
        for (int k = 0; k < Din; k++) a = fmaf(xs[r*Din + k], Ws[k*Dd + d], a);
        h[(size_t)(m0+r)*Dd + d] = __float2half(a);
    }
}

// ---------------- FP16 GEMM (128x64 tile, 32x32 warp tile, 3 CTAs/SM) ----------------
#define AST 20
#define B2STN 68              // u64 row stride in smem (136 u32 = 8 mod 32: conflict-free)
#define A_SZ (128*AST)        // 2560 u32 per stage
#define B_SZN (8*B2STN*2)     // 1088 u32 per stage (8 u64 rows x 68)
#define TG_SMEM (4*(A_SZ + B_SZN)*4)   // 58368 bytes

template<int RELU>
__global__ __launch_bounds__(256, 3) void tgemm_kernel(
    const uint32_t* __restrict__ A, const uint32_t* __restrict__ Wp,
    const float* __restrict__ bias, uint32_t* __restrict__ C,
    int M, int Nd, int Kd)
{
    const int Kd2 = Kd >> 1, Nd2 = Nd >> 1;
    extern __shared__ uint32_t dsm[];
    uint32_t* Asm = dsm;
    uint32_t* Bsm = dsm + 4*A_SZ;

    const int tid = threadIdx.x;
    const int warp = tid >> 5;
    const int lane = tid & 31;
    const int bm = blockIdx.y, bn = blockIdx.x;
    const int wm = warp & 3;          // 4 m-warps x 32 rows
    const int wn = warp >> 2;         // 2 n-warps x 32 cols
    const int qid = lane >> 2;
    const int tig = lane & 3;

    const int a_r0 = tid >> 1, a_c0 = (tid & 1) << 3;
    const int b_r = tid >> 5, b_c = tid & 31;   // B loader: u64 row, 16B chunk (2 u64)

    const int row_sel = (lane & 7) + ((lane >> 3) & 1) * 8;
    const int col_sel = (lane >> 4) * 4;
    const uint32_t a_lm_off = (uint32_t)(((wm*32 + row_sel)*AST + col_sel) * 4);
    const uint32_t asm_base = (uint32_t)__cvta_generic_to_shared(Asm);

    const uint32_t* Ap = A + (size_t)(bm*128)*Kd2;
    const uint64_t* Bp = (const uint64_t*)Wp + (size_t)bn*64;

    float acc[2][4][4];
#pragma unroll
    for (int mt = 0; mt < 2; mt++)
#pragma unroll
        for (int nt = 0; nt < 4; nt++)
#pragma unroll
            for (int i = 0; i < 4; i++) acc[mt][nt][i] = 0.f;

    const int niter = Kd >> 5;
    const int npair = niter >> 1;

#define LOAD_TILE(ck, s) do {                                                      \
        int _ck = (ck), _s = (s);                                                  \
        const uint32_t* Ap2 = Ap + _ck*16;                                         \
        const uint64_t* Bp2 = Bp + (size_t)(_ck*8 + b_r)*Nd;                       \
        cp16(&Asm[_s*A_SZ + a_r0*AST + a_c0],     Ap2 + (size_t)a_r0*Kd2 + a_c0);  \
        cp16(&Asm[_s*A_SZ + a_r0*AST + a_c0 + 4], Ap2 + (size_t)a_r0*Kd2 + a_c0 + 4); \
        cp16(&Bsm[_s*B_SZN + b_r*(2*B2STN) + b_c*4], Bp2 + b_c*2);                 \
    } while (0)

    LOAD_TILE(0, 0);
    LOAD_TILE(1, 1);
    CP_COMMIT();

    for (int p = 0; p < npair; p++) {
        CP_WAIT(0);
        __syncthreads();

        if (p + 1 < npair) {
            int sb = ((p + 1) & 1) << 1;
            LOAD_TILE(2*(p+1),     sb);
            LOAD_TILE(2*(p+1) + 1, sb + 1);
        }
        CP_COMMIT();

#pragma unroll
        for (int half = 0; half < 2; half++) {
            const int stg = ((p & 1) << 1) + half;
            const uint32_t stage_base = asm_base + (uint32_t)(stg*A_SZ)*4;
            const uint2* B2 = (const uint2*)(Bsm + stg*B_SZN);
#pragma unroll
            for (int ks = 0; ks < 2; ks++) {
                uint32_t afrag[2][4];
#pragma unroll
                for (int mt = 0; mt < 2; mt++)
                    ldmx4(afrag[mt], stage_base + a_lm_off + (uint32_t)((mt*16*AST + ks*8)*4));
#pragma unroll
                for (int nt = 0; nt < 4; nt++) {
                    int cn = wn*32 + nt*8 + qid;
                    uint2 bv = B2[(ks*4 + tig)*B2STN + cn];
                    uint32_t bfrag[2] = { bv.x, bv.y };
#pragma unroll
                    for (int mt = 0; mt < 2; mt++)
                        mma_f16(acc[mt][nt], afrag[mt], bfrag);
                }
            }
        }
    }
#undef LOAD_TILE

#pragma unroll
    for (int mt = 0; mt < 2; mt++) {
        int r0 = bm*128 + wm*32 + mt*16 + qid;
#pragma unroll
        for (int nt = 0; nt < 4; nt++) {
            int c0 = bn*64 + wn*32 + nt*8 + 2*tig;
            float b0 = bias ? bias[c0]   : 0.f;
            float b1 = bias ? bias[c0+1] : 0.f;
            float v0 = acc[mt][nt][0] + b0, v1 = acc[mt][nt][1] + b1;
            float v2 = acc[mt][nt][2] + b0, v3 = acc[mt][nt][3] + b1;
            if (RELU) {
                v0 = fmaxf(v0, 0.f); v1 = fmaxf(v1, 0.f);
                v2 = fmaxf(v2, 0.f); v3 = fmaxf(v3, 0.f);
            }
            int cu = c0 >> 1;
            C[(size_t)r0*Nd2 + cu]     = pkhf(v0, v1);
            C[(size_t)(r0+8)*Nd2 + cu] = pkhf(v2, v3);
        }
    }
}

// ---------------- fused GEMM (64x256 tile) + LN epilogue OR scores epilogue ----------------
#define ASTF 20
#define B2STF 260
#define A_SZF (64*ASTF)
#define B_SZF (8*B2STF*2)
#define TL_SMEM (4*(A_SZF + B_SZF)*4)   // 87040 bytes

template<int MODE>
__global__ __launch_bounds__(256, 2) void tgemm_ln_kernel(
    const uint32_t* __restrict__ A, const uint32_t* __restrict__ Wp,
    const float* __restrict__ bias, uint32_t* __restrict__ Hio,
    int Kd,
    const float* __restrict__ g, const float* __restrict__ bta,
    const float* __restrict__ qvv, float* __restrict__ sc)
{
    const int Kd2 = Kd >> 1;
    extern __shared__ uint32_t dsm[];
    uint32_t* Asm = dsm;
    uint32_t* Bsm = dsm + 4*A_SZF;

    const int tid = threadIdx.x;
    const int warp = tid >> 5;
    const int lane = tid & 31;
    const int bm = blockIdx.x;
    const int wm = warp & 1;
    const int wn = warp >> 1;
    const int qid = lane >> 2;
    const int tig = lane & 3;

    const int a_r0 = tid >> 2, a_c0 = (tid & 3) << 2;
    const int b_r = tid >> 5, b_c = tid & 31;

    const int row_sel = (lane & 7) + ((lane >> 3) & 1) * 8;
    const int col_sel = (lane >> 4) * 4;
    const uint32_t a_lm_off = (uint32_t)(((wm*32 + row_sel)*ASTF + col_sel) * 4);
    const uint32_t asm_base = (uint32_t)__cvta_generic_to_shared(Asm);

    const uint32_t* Ap = A + (size_t)(bm*64)*Kd2;
    const uint64_t* Bp = (const uint64_t*)Wp;

    float acc[2][8][4];
#pragma unroll
    for (int mt = 0; mt < 2; mt++)
#pragma unroll
        for (int nt = 0; nt < 8; nt++)
#pragma unroll
            for (int i = 0; i < 4; i++) acc[mt][nt][i] = 0.f;

    const int niter = Kd >> 5;
    const int npair = niter >> 1;

#define LOAD_TILEF(ck, s) do {                                                     \
        int _ck = (ck), _s = (s);                                                  \
        const uint32_t* Ap2 = Ap + _ck*16;                                         \
        const uint64_t* Bp2 = Bp + (size_t)(_ck*8 + b_r)*256;                      \
        cp16(&Asm[_s*A_SZF + a_r0*ASTF + a_c0], Ap2 + (size_t)a_r0*Kd2 + a_c0);    \
        _Pragma("unroll")                                                          \
        for (int _j = 0; _j < 4; _j++)                                             \
            cp16(&Bsm[_s*B_SZF + b_r*(2*B2STF) + (b_c + 32*_j)*4],                 \
                 Bp2 + (b_c + 32*_j)*2);                                           \
    } while (0)

    LOAD_TILEF(0, 0);
    LOAD_TILEF(1, 1);
    CP_COMMIT();

    for (int p = 0; p < npair; p++) {
        CP_WAIT(0);
        __syncthreads();

        if (p + 1 < npair) {
            int sb = ((p + 1) & 1) << 1;
            LOAD_TILEF(2*(p+1),     sb);
            LOAD_TILEF(2*(p+1) + 1, sb + 1);
        }
        CP_COMMIT();

#pragma unroll
        for (int half = 0; half < 2; half++) {
            const int stg = ((p & 1) << 1) + half;
            const uint32_t stage_base = asm_base + (uint32_t)(stg*A_SZF)*4;
            const uint2* B2 = (const uint2*)(Bsm + stg*B_SZF);
#pragma unroll
            for (int ks = 0; ks < 2; ks++) {
                uint32_t afrag[2][4];
#pragma unroll
                for (int mt = 0; mt < 2; mt++)
                    ldmx4(afrag[mt], stage_base + a_lm_off + (uint32_t)((mt*16*ASTF + ks*8)*4));
#pragma unroll
                for (int nt = 0; nt < 8; nt++) {
                    int cn = wn*64 + nt*8 + qid;
                    uint2 bv = B2[(ks*4 + tig)*B2STF + cn];
                    uint32_t bfrag[2] = { bv.x, bv.y };
#pragma unroll
                    for (int mt = 0; mt < 2; mt++)
                        mma_f16(acc[mt][nt], afrag[mt], bfrag);
                }
            }
        }
    }
#undef LOAD_TILEF

    __syncthreads();
    float2* Sf2 = (float2*)dsm;           // [64][132] float2
#pragma unroll
    for (int mt = 0; mt < 2; mt++) {
        int rl0 = wm*32 + mt*16 + qid;
#pragma unroll
        for (int nt = 0; nt < 8; nt++) {
            int cu = wn*32 + nt*4 + tig;
            float b0 = 0.f, b1 = 0.f;
            if (MODE == 0 && bias) { b0 = bias[2*cu]; b1 = bias[2*cu+1]; }
            float v0 = acc[mt][nt][0] + b0, v1 = acc[mt][nt][1] + b1;
            float v2 = acc[mt][nt][2] + b0, v3 = acc[mt][nt][3] + b1;
            if (MODE == 0) {
                uint32_t h0 = Hio[(size_t)(bm*64 + rl0)*128 + cu];
                uint32_t h1 = Hio[(size_t)(bm*64 + rl0 + 8)*128 + cu];
                __half2 hh0 = *(__half2*)&h0;
                __half2 hh1 = *(__half2*)&h1;
                v0 += __half2float(hh0.x); v1 += __half2float(hh0.y);
                v2 += __half2float(hh1.x); v3 += __half2float(hh1.y);
            }
            float2 p0; p0.x = v0; p0.y = v1;
            float2 p1; p1.x = v2; p1.y = v3;
            Sf2[rl0*132 + cu]       = p0;
            Sf2[(rl0 + 8)*132 + cu] = p1;
        }
    }
    __syncthreads();

    if (MODE == 0) {
#pragma unroll
        for (int r = 0; r < 8; r++) {
            int row = warp*8 + r;
            float v[8];
            float s = 0.f;
#pragma unroll
            for (int j = 0; j < 4; j++) {
                float2 t = Sf2[row*132 + lane + j*32];
                v[2*j] = t.x; v[2*j+1] = t.y;
                s += t.x + t.y;
            }
#pragma unroll
            for (int o = 16; o; o >>= 1) s += __shfl_xor_sync(0xffffffffu, s, o);
            float mean = s * (1.f/256.f);
            float vs = 0.f;
#pragma unroll
            for (int i = 0; i < 8; i++) { float d = v[i]-mean; vs = fmaf(d, d, vs); }
#pragma unroll
            for (int o = 16; o; o >>= 1) vs += __shfl_xor_sync(0xffffffffu, vs, o);
            float rstd = rsqrtf(vs * (1.f/256.f) + 1e-5f);
#pragma unroll
            for (int j = 0; j < 4; j++) {
                int c = 2*(lane + j*32);
                float o0 = (v[2*j]  -mean)*rstd*g[c]   + bta[c];
                float o1 = (v[2*j+1]-mean)*rstd*g[c+1] + bta[c+1];
                Hio[(size_t)(bm*64 + row)*128 + lane + j*32] = pkhf(o0, o1);
            }
        }
    } else {
        const int b = (bm*64) >> 10;
        const float* qrow = qvv + b*Dd;
#pragma unroll
        for (int r = 0; r < 8; r++) {
            int row = warp*8 + r;
            float s = 0.f;
#pragma unroll
            for (int j = 0; j < 4; j++) {
                float2 t = Sf2[row*132 + lane + j*32];
                int c = 2*(lane + j*32);
                s = fmaf(t.x, qrow[c], s);
                s = fmaf(t.y, qrow[c+1], s);
            }
#pragma unroll
            for (int o = 16; o; o >>= 1) s += __shfl_xor_sync(0xffffffffu, s, o);
            if (lane == 0) sc[bm*64 + row] = s * 0.0625f;
        }
    }
}

// ---------------- fp16 flash attention: cp.async double-buffered K + raw V ----------------
#define QKV_RS 384
#define O_RS   128
#define KST 36
#define VRS 32
#define VST 72
#define PST 36
#define K_SZ (64*KST)
#define VR_SZ (64*VRS)
#define ATT_SMEM ((2*K_SZ + 2*VR_SZ + 32*VST + 8*16*PST)*4)

__global__ void __launch_bounds__(256) attn_mma_kernel(
    const uint32_t* __restrict__ QKV, uint32_t* __restrict__ O)
{
    extern __shared__ uint32_t sm[];
    uint32_t* Kst  = sm;
    uint32_t* Vraw = sm + 2*K_SZ;
    uint32_t* Vs   = sm + 2*K_SZ + 2*VR_SZ;
    const int tid = threadIdx.x;
    const int warp = tid >> 5, lane = tid & 31;
    const int qid = lane >> 2, tig = lane & 3;
    uint32_t* Psw = sm + 2*K_SZ + 2*VR_SZ + 32*VST + warp*16*PST;

    const int qt = blockIdx.x, head = blockIdx.y, b = blockIdx.z;
    const size_t qbase = ((size_t)b*Nn)*QKV_RS + head*(DH/2);
    const size_t kbase = qbase + 128;
    const size_t vbase = qbase + 256;
    const size_t obase = ((size_t)b*Nn)*O_RS + head*(DH/2);
    const int q0 = qt*128 + warp*16;

    uint32_t qa[4][4];
#pragma unroll
    for (int s = 0; s < 4; s++) {
        qa[s][0] = QKV[qbase + (size_t)(q0+qid  )*QKV_RS + s*8 + tig];
        qa[s][1] = QKV[qbase + (size_t)(q0+qid+8)*QKV_RS + s*8 + tig];
        qa[s][2] = QKV[qbase + (size_t)(q0+qid  )*QKV_RS + s*8 + tig + 4];
        qa[s][3] = QKV[qbase + (size_t)(q0+qid+8)*QKV_RS + s*8 + tig + 4];
    }

    float oacc[8][4];
#pragma unroll
    for (int dn = 0; dn < 8; dn++)
#pragma unroll
        for (int i = 0; i < 4; i++) oacc[dn][i] = 0.f;
    float m0 = -1e30f, m1 = -1e30f, l0 = 0.f, l1 = 0.f;
    const float scale = 0.125f;

    const int kr = tid >> 3, kq = (tid & 7) << 2;
    const int vr = tid >> 2, vq = (tid & 3) << 3;
    const int np = tid >> 3, dq = tid & 7;

    cp16(&Kst[kr*KST + kq],       QKV + kbase + (size_t)kr*QKV_RS + kq);
    cp16(&Kst[(kr+32)*KST + kq],  QKV + kbase + (size_t)(kr+32)*QKV_RS + kq);
    cp16(&Vraw[vr*VRS + vq],      QKV + vbase + (size_t)vr*QKV_RS + vq);
    cp16(&Vraw[vr*VRS + vq + 4],  QKV + vbase + (size_t)vr*QKV_RS + vq + 4);
    CP_COMMIT();

    int buf = 0;
    const int ntile = Nn/64;
    for (int jt = 0; jt < ntile; jt++) {
        if (jt + 1 < ntile) {
            int j1 = (jt+1)*64, nb = buf ^ 1;
            cp16(&Kst[nb*K_SZ + kr*KST + kq],      QKV + kbase + (size_t)(j1+kr)*QKV_RS + kq);
            cp16(&Kst[nb*K_SZ + (kr+32)*KST + kq], QKV + kbase + (size_t)(j1+kr+32)*QKV_RS + kq);
            cp16(&Vraw[nb*VR_SZ + vr*VRS + vq],    QKV + vbase + (size_t)(j1+vr)*QKV_RS + vq);
            cp16(&Vraw[nb*VR_SZ + vr*VRS + vq+4],  QKV + vbase + (size_t)(j1+vr)*QKV_RS + vq+4);
        }
        CP_COMMIT();
        CP_WAIT(1);
        __syncthreads();

        const uint32_t* Ks = &Kst[buf*K_SZ];
        const uint32_t* Vr = &Vraw[buf*VR_SZ];

        {
            uint4 r0 = *(const uint4*)(Vr + (2*np  )*VRS + dq*4);
            uint4 r1 = *(const uint4*)(Vr + (2*np+1)*VRS + dq*4);
            uint4 o0, o1;
            o0.x = __byte_perm(r0.x, r1.x, 0x5410); o0.y = __byte_perm(r0.x, r1.x, 0x7632);
            o0.z = __byte_perm(r0.y, r1.y, 0x5410); o0.w = __byte_perm(r0.y, r1.y, 0x7632);
            o1.x = __byte_perm(r0.z, r1.z, 0x5410); o1.y = __byte_perm(r0.z, r1.z, 0x7632);
            o1.z = __byte_perm(r0.w, r1.w, 0x5410); o1.w = __byte_perm(r0.w, r1.w, 0x7632);
            *(uint4*)&Vs[np*VST + dq*8]     = o0;
            *(uint4*)&Vs[np*VST + dq*8 + 4] = o1;
        }

        float sacc[8][4];
#pragma unroll
        for (int nt = 0; nt < 8; nt++)
#pragma unroll
            for (int i = 0; i < 4; i++) sacc[nt][i] = 0.f;
#pragma unroll
        for (int s = 0; s < 4; s++) {
#pragma unroll
            for (int nt = 0; nt < 8; nt++) {
                uint32_t bfrag[2];
                bfrag[0] = Ks[(nt*8+qid)*KST + s*8 + tig];
                bfrag[1] = Ks[(nt*8+qid)*KST + s*8 + tig + 4];
                mma_f16(sacc[nt], qa[s], bfrag);
            }
        }
#pragma unroll
        for (int nt = 0; nt < 8; nt++)
#pragma unroll
            for (int i = 0; i < 4; i++) sacc[nt][i] *= scale;

        float tm0 = -1e30f, tm1 = -1e30f;
#pragma unroll
        for (int nt = 0; nt < 8; nt++) {
            tm0 = fmaxf(tm0, fmaxf(sacc[nt][0], sacc[nt][1]));
            tm1 = fmaxf(tm1, fmaxf(sacc[nt][2], sacc[nt][3]));
        }
        tm0 = fmaxf(tm0, __shfl_xor_sync(0xffffffffu, tm0, 1));
        tm0 = fmaxf(tm0, __shfl_xor_sync(0xffffffffu, tm0, 2));
        tm1 = fmaxf(tm1, __shfl_xor_sync(0xffffffffu, tm1, 1));
        tm1 = fmaxf(tm1, __shfl_xor_sync(0xffffffffu, tm1, 2));
        float mn0 = fmaxf(m0, tm0), mn1 = fmaxf(m1, tm1);
        float c0 = __expf(m0 - mn0), c1 = __expf(m1 - mn1);
        m0 = mn0; m1 = mn1;
        l0 *= c0; l1 *= c1;
#pragma unroll
        for (int dn = 0; dn < 8; dn++) {
            oacc[dn][0] *= c0; oacc[dn][1] *= c0;
            oacc[dn][2] *= c1; oacc[dn][3] *= c1;
        }
#pragma unroll
        for (int nt = 0; nt < 8; nt++) {
            float p0 = __expf(sacc[nt][0] - m0);
            float p1 = __expf(sacc[nt][1] - m0);
            float p2 = __expf(sacc[nt][2] - m1);
            float p3 = __expf(sacc[nt][3] - m1);
            l0 += p0 + p1; l1 += p2 + p3;
            Psw[qid*PST     + nt*4 + tig] = pkhf(p0, p1);
            Psw[(qid+8)*PST + nt*4 + tig] = pkhf(p2, p3);
        }
        __syncthreads();

#pragma unroll
        for (int sj = 0; sj < 4; sj++) {
            uint32_t afrag[4];
            afrag[0] = Psw[qid*PST     + sj*8 + tig];
            afrag[1] = Psw[(qid+8)*PST + sj*8 + tig];
            afrag[2] = Psw[qid*PST     + sj*8 + tig + 4];
            afrag[3] = Psw[(qid+8)*PST + sj*8 + tig + 4];
#pragma unroll
            for (int dn = 0; dn < 8; dn++) {
                uint32_t bfrag[2];
                bfrag[0] = Vs[(sj*8+tig  )*VST + dn*8 + qid];
                bfrag[1] = Vs[(sj*8+tig+4)*VST + dn*8 + qid];
                mma_f16(oacc[dn], afrag, bfrag);
            }
        }
        buf ^= 1;
    }

    l0 += __shfl_xor_sync(0xffffffffu, l0, 1);
    l0 += __shfl_xor_sync(0xffffffffu, l0, 2);
    l1 += __shfl_xor_sync(0xffffffffu, l1, 1);
    l1 += __shfl_xor_sync(0xffffffffu, l1, 2);
    float inv0 = 1.f / l0, inv1 = 1.f / l1;
#pragma unroll
    for (int dn = 0; dn < 8; dn++) {
        int cu = dn*4 + tig;
        O[obase + (size_t)(q0+qid  )*O_RS + cu] = pkhf(oacc[dn][0]*inv0, oacc[dn][1]*inv0);
        O[obase + (size_t)(q0+qid+8)*O_RS + cu] = pkhf(oacc[dn][2]*inv1, oacc[dn][3]*inv1);
    }
}

// ---------------- h_mean: 4 partial blocks per batch + atomics ----------------
__global__ void hmean_kernel(const __half* __restrict__ h, float* __restrict__ hm)
{
    int b = blockIdx.y, seg = blockIdx.x;
    int d = threadIdx.x;
    const __half* p = h + ((size_t)b*Nn + seg*256)*Dd + d;
    float s = 0.f;
#pragma unroll 8
    for (int n = 0; n < 256; n++) s += __half2float(p[(size_t)n*Dd]);
    atomicAdd(&hm[b*Dd + d], s * (1.f/1024.f));
}

// ---------------- small row GEMM (fp32) ----------------
template<int RELU>
__global__ void rowgemm_kernel(const float* __restrict__ A, const float* __restrict__ W,
                               const float* __restrict__ bias, float* __restrict__ C,
                               int Kd, int Nd)
{
    int b = blockIdx.x;
    __shared__ float xs[1024];
    for (int i = threadIdx.x; i < Kd; i += blockDim.x) xs[i] = A[(size_t)b*Kd + i];
    __syncthreads();
    for (int d = threadIdx.x; d < Nd; d += blockDim.x) {
        float acc = bias ? bias[d] : 0.f;
        for (int k = 0; k < Kd; k++) acc = fmaf(xs[k], W[(size_t)k*Nd + d], acc);
        if (RELU) acc = fmaxf(acc, 0.f);
        C[(size_t)b*Nd + d] = acc;
    }
}

// ---------------- finale: softmaxes + fast top-64 + sel ----------------
__global__ void finale_kernel(const float* __restrict__ scores, const float* __restrict__ gumbel,
                              const float* __restrict__ logits,
                              float* __restrict__ out_w, float* __restrict__ out_idx,
                              float* __restrict__ out_sel)
{
    int b = blockIdx.x, tid = threadIdx.x;
    const int wid = tid >> 5, lane = tid & 31;
    __shared__ float w[1024];
    __shared__ float al[1024];
    __shared__ float red[256];
    __shared__ unsigned long long kred[8];
    __shared__ int selidx[64];

    float lm = -1e30f;
    for (int i = tid; i < 1024; i += 256) {
        float v = (scores[b*Nn+i] + gumbel[b*Nn+i]) * 2.0f;
        w[i] = v; lm = fmaxf(lm, v);
    }
    red[tid] = lm; __syncthreads();
    for (int s = 128; s; s >>= 1) { if (tid < s) red[tid] = fmaxf(red[tid], red[tid+s]); __syncthreads(); }
    float M = red[0]; __syncthreads();
    float ls = 0.f;
    for (int i = tid; i < 1024; i += 256) { float e = __expf(w[i]-M); w[i] = e; ls += e; }
    red[tid] = ls; __syncthreads();
    for (int s = 128; s; s >>= 1) { if (tid < s) red[tid] += red[tid+s]; __syncthreads(); }
    float invS = 1.f / red[0]; __syncthreads();
    for (int i = tid; i < 1024; i += 256) {
        float wi = w[i]*invS; w[i] = wi; out_w[b*Nn+i] = wi;
    }

    lm = -1e30f;
    for (int i = tid; i < 1024; i += 256) { float v = logits[b*Nn+i]; al[i] = v; lm = fmaxf(lm, v); }
    __syncthreads();
    red[tid] = lm; __syncthreads();
    for (int s = 128; s; s >>= 1) { if (tid < s) red[tid] = fmaxf(red[tid], red[tid+s]); __syncthreads(); }
    M = red[0]; __syncthreads();
    ls = 0.f;
    for (int i = tid; i < 1024; i += 256) { float e = __expf(al[i]-M); al[i] = e; ls += e; }
    red[tid] = ls; __syncthreads();
    for (int s = 128; s; s >>= 1) { if (tid < s) red[tid] += red[tid+s]; __syncthreads(); }
    invS = 1.f / red[0]; __syncthreads();
    for (int i = tid; i < 1024; i += 256) al[i] *= invS;
    __syncthreads();

    for (int kk = 0; kk < 64; kk++) {
        unsigned long long best = 0ull;
#pragma unroll
        for (int t = 0; t < 4; t++) {
            int i = tid + t*256;
            float v = w[i];
            unsigned long long key = (v < 0.f) ? 0ull
                : (((unsigned long long)__float_as_uint(v)) << 32) | (unsigned long long)(1023 - i);
            best = (key > best) ? key : best;
        }
#pragma unroll
        for (int o = 16; o; o >>= 1) {
            unsigned long long ot = __shfl_xor_sync(0xffffffffu, best, o);
            best = (ot > best) ? ot : best;
        }
        if (lane == 0) kred[wid] = best;
        __syncthreads();
        if (tid == 0) {
            unsigned long long bb2 = kred[0];
#pragma unroll
            for (int j = 1; j < 8; j++) if (kred[j] > bb2) bb2 = kred[j];
            int idx = 1023 - (int)(bb2 & 0x3FFull);
            selidx[kk] = idx;
            w[idx] = -1.0f;
        }
        __syncthreads();
    }

    float sv = 0.f;
    if (tid < 64) sv = al[selidx[tid]];
    red[tid] = (tid < 64) ? sv : 0.f; __syncthreads();
    for (int s = 128; s; s >>= 1) { if (tid < s) red[tid] += red[tid+s]; __syncthreads(); }
    float inv = 1.f / (red[0] + 1e-12f);
    if (tid < 64) {
        out_idx[b*64 + tid] = (float)selidx[tid];
        out_sel[b*64 + tid] = sv * inv;
    }
}

// ---------------- launch ----------------
extern "C" void kernel_launch(void* const* d_in, const int* in_sizes, int n_in,
                              void* d_out, int out_size)
{
    const float* x       = (const float*)d_in[0];
    const float* gumbel  = (const float*)d_in[1];
    const float* emb_W   = (const float*)d_in[2];
    const float* emb_b   = (const float*)d_in[3];
    const float* Wq      = (const float*)d_in[4];
    const float* Wk      = (const float*)d_in[5];
    const float* Wv      = (const float*)d_in[6];
    const float* Wo      = (const float*)d_in[7];
    const float* ln1_g   = (const float*)d_in[8];
    const float* ln1_b   = (const float*)d_in[9];
    const float* ln2_g   = (const float*)d_in[10];
    const float* ln2_b   = (const float*)d_in[11];
    const float* ffn_W1  = (const float*)d_in[12];
    const float* ffn_b1  = (const float*)d_in[13];
    const float* ffn_W2  = (const float*)d_in[14];
    const float* ffn_b2  = (const float*)d_in[15];
    const float* sha_Wq  = (const float*)d_in[16];
    const float* sha_Wk  = (const float*)d_in[17];
    const float* alloc_W1= (const float*)d_in[18];
    const float* alloc_b1= (const float*)d_in[19];
    const float* alloc_W2= (const float*)d_in[20];
    const float* alloc_b2= (const float*)d_in[21];

    __half *h, *scr;
    uint32_t* wpk;
    float *hmean, *qv, *t1, *logits, *scores;
    cudaGetSymbolAddress((void**)&h,      g_h);
    cudaGetSymbolAddress((void**)&scr,    g_scr);
    cudaGetSymbolAddress((void**)&wpk,    g_wpk);
    cudaGetSymbolAddress((void**)&hmean,  g_hmean);
    cudaGetSymbolAddress((void**)&qv,     g_qv);
    cudaGetSymbolAddress((void**)&t1,     g_t1);
    cudaGetSymbolAddress((void**)&logits, g_logits);
    cudaGetSymbolAddress((void**)&scores, g_scores);

    static int cfg_done = 0;
    if (!cfg_done) {
        cudaFuncSetAttribute(tgemm_kernel<0>,
                             cudaFuncAttributeMaxDynamicSharedMemorySize, TG_SMEM);
        cudaFuncSetAttribute(tgemm_kernel<1>,
                             cudaFuncAttributeMaxDynamicSharedMemorySize, TG_SMEM);
        cudaFuncSetAttribute(tgemm_ln_kernel<0>,
                             cudaFuncAttributeMaxDynamicSharedMemorySize, TL_SMEM);
        cudaFuncSetAttribute(tgemm_ln_kernel<1>,
                             cudaFuncAttributeMaxDynamicSharedMemorySize, TL_SMEM);
        cudaFuncSetAttribute(attn_mma_kernel,
                             cudaFuncAttributeMaxDynamicSharedMemorySize, ATT_SMEM);
        cfg_done = 1;
    }

    packall_kernel<<<dim3(1536, 7), 256>>>(Wq, Wk, Wv, Wo, ffn_W1, ffn_W2, sha_Wk, wpk);
    zeroh_kernel<<<Bb*Dd/256, 256>>>(hmean);

    __half* qkv = scr;                          // [M][768]
    __half* ao  = scr + (size_t)MM*768;         // [M][256]

    embed_kernel<<<MM/16, 256>>>(x, emb_W, emb_b, h);

    const dim3 gQKV(768/64, MM/128);   // (12,512)
    const dim3 gF1(DFF/64, MM/128);    // (16,512)

    for (int i = 0; i < Ll; i++) {
        tgemm_kernel<0><<<gQKV, 256, TG_SMEM>>>((const uint32_t*)h, wpk + OFF_QKV + (size_t)i*128*768, nullptr, (uint32_t*)qkv, MM, 768, Dd);
        attn_mma_kernel<<<dim3(Nn/128, Hh, Bb), 256, ATT_SMEM>>>((const uint32_t*)qkv, (uint32_t*)ao);
        tgemm_ln_kernel<0><<<MM/64, 256, TL_SMEM>>>(
            (const uint32_t*)ao, wpk + OFF_WO + (size_t)i*128*256, nullptr, (uint32_t*)h,
            Dd, ln1_g + i*Dd, ln1_b + i*Dd, nullptr, nullptr);
        tgemm_kernel<1><<<gF1, 256, TG_SMEM>>>((const uint32_t*)h, wpk + OFF_W1 + (size_t)i*128*1024, ffn_b1 + i*DFF, (uint32_t*)scr, MM, DFF, Dd);
        tgemm_ln_kernel<0><<<MM/64, 256, TL_SMEM>>>(
            (const uint32_t*)scr, wpk + OFF_W2 + (size_t)i*512*256, ffn_b2 + i*Dd, (uint32_t*)h,
            DFF, ln2_g + i*Dd, ln2_b + i*Dd, nullptr, nullptr);
    }

    hmean_kernel<<<dim3(4, Bb), 256>>>(h, hmean);
    rowgemm_kernel<0><<<Bb, 256>>>(hmean, sha_Wq, nullptr, qv, Dd, Dd);
    tgemm_ln_kernel<1><<<MM/64, 256, TL_SMEM>>>(
        (const uint32_t*)h, wpk + OFF_SHA, nullptr, (uint32_t*)h,
        Dd, nullptr, nullptr, qv, scores);
    rowgemm_kernel<1><<<Bb, 256>>>(hmean, alloc_W1, alloc_b1, t1, Dd, Dd);
    rowgemm_kernel<0><<<Bb, 256>>>(t1, alloc_W2, alloc_b2, logits, Dd, Nn);

    float* out = (float*)d_out;
    finale_kernel<<<Bb, 256>>>(scores, gumbel, logits,
                               out,
                               out + Bb*Nn,
                               out + Bb*Nn + Bb*Kk);
}

// round 16
// speedup vs baseline: 1.5996x; 1.5996x over previous
#include <cuda_runtime.h>
#include <cuda_fp16.h>
#include <cstdint>

// ---------------- problem dims ----------------
#define Bb 64
#define Nn 1024
#define Din 16
#define Dd 256
#define Hh 4
#define DH 64
#define Ll 3
#define DFF 1024
#define Kk 64
#define MM (Bb*Nn)          // 65536 rows

// ---------------- scratch (static device memory) ----------------
__device__ __half g_h[MM*Dd];           // 32 MB hidden state (fp16)
__device__ __half g_scr[MM*DFF];        // 128 MB qkv|ao or ffn hidden
__device__ uint32_t g_wpk[1212416];     // packed fp16 weights (u64-fragment layout)
__device__ float g_hmean[Bb*Dd];
__device__ float g_qv[Bb*Dd];
__device__ float g_t1[Bb*Dd];
__device__ float g_logits[Bb*Nn];
__device__ float g_scores[Bb*Nn];

// packed-weight offsets (uint32 units)
#define OFF_QKV  0            // 3 x [64 u64-rows][768]
#define OFF_WO   294912       // 3 x [64][256]
#define OFF_W1   393216       // 3 x [64][1024]
#define OFF_W2   786432       // 3 x [256][256]
#define OFF_SHA  1179648      // [64][256]

__device__ __forceinline__ uint32_t pkhf(float lo, float hi) {
    uint32_t r;
    asm("cvt.rn.f16x2.f32 %0, %1, %2;" : "=r"(r) : "f"(hi), "f"(lo));
    return r;
}

__device__ __forceinline__ void mma_f16(float* c, const uint32_t* a, const uint32_t* b) {
    asm volatile(
        "mma.sync.aligned.m16n8k16.row.col.f32.f16.f16.f32 "
        "{%0,%1,%2,%3}, {%4,%5,%6,%7}, {%8,%9}, {%0,%1,%2,%3};"
        : "+f"(c[0]), "+f"(c[1]), "+f"(c[2]), "+f"(c[3])
        : "r"(a[0]), "r"(a[1]), "r"(a[2]), "r"(a[3]), "r"(b[0]), "r"(b[1]));
}

__device__ __forceinline__ void ldmx4(uint32_t* r, uint32_t saddr) {
    asm volatile("ldmatrix.sync.aligned.m8n8.x4.shared.b16 {%0,%1,%2,%3}, [%4];"
        : "=r"(r[0]), "=r"(r[1]), "=r"(r[2]), "=r"(r[3]) : "r"(saddr));
}

__device__ __forceinline__ void cp16(void* smem, const void* gmem) {
    uint32_t s = (uint32_t)__cvta_generic_to_shared(smem);
    asm volatile("cp.async.cg.shared.global [%0], [%1], 16;" :: "r"(s), "l"(gmem));
}
#define CP_COMMIT() asm volatile("cp.async.commit_group;")
#define CP_WAIT(n)  asm volatile("cp.async.wait_group %0;" :: "n"(n))

// ---------------- fused weight pack: all 7 weights in one launch ----------------
__global__ void packall_kernel(const float* __restrict__ Wq, const float* __restrict__ Wk,
                               const float* __restrict__ Wv, const float* __restrict__ Wo,
                               const float* __restrict__ W1, const float* __restrict__ W2,
                               const float* __restrict__ sha, uint32_t* __restrict__ dst)
{
    int seg = blockIdx.y;
    int i = blockIdx.x*256 + threadIdx.x;
    const float* src; int Nsrc, NdT, colOff, KN, KNh, lds, total, dstOff;
    switch (seg) {
        case 0: src=Wq;  dstOff=OFF_QKV; Nsrc=256;  NdT=768;  colOff=0;   KN=65536;  KNh=32768;  lds=98304;  total=98304;  break;
        case 1: src=Wk;  dstOff=OFF_QKV; Nsrc=256;  NdT=768;  colOff=256; KN=65536;  KNh=32768;  lds=98304;  total=98304;  break;
        case 2: src=Wv;  dstOff=OFF_QKV; Nsrc=256;  NdT=768;  colOff=512; KN=65536;  KNh=32768;  lds=98304;  total=98304;  break;
        case 3: src=Wo;  dstOff=OFF_WO;  Nsrc=256;  NdT=256;  colOff=0;   KN=65536;  KNh=32768;  lds=32768;  total=98304;  break;
        case 4: src=W1;  dstOff=OFF_W1;  Nsrc=1024; NdT=1024; colOff=0;   KN=262144; KNh=131072; lds=131072; total=393216; break;
        case 5: src=W2;  dstOff=OFF_W2;  Nsrc=256;  NdT=256;  colOff=0;   KN=262144; KNh=131072; lds=131072; total=393216; break;
        default:src=sha; dstOff=OFF_SHA; Nsrc=256;  NdT=256;  colOff=0;   KN=65536;  KNh=32768;  lds=32768;  total=32768;  break;
    }
    if (i >= total) return;
    int l = i / KNh;
    int rem = i - l*KNh;
    int kp = rem / Nsrc, n = rem - kp*Nsrc;
    int t = kp >> 4, r = kp & 15;
    int j = ((r >> 3) << 2) | (r & 3);
    int half = (r >> 2) & 1;
    const float* s = src + (size_t)l*KN;
    dst[(size_t)dstOff + (size_t)l*lds
        + ((size_t)(t*8 + j)*NdT + colOff + n)*2 + half] =
        pkhf(s[(size_t)(2*kp)*Nsrc + n], s[(size_t)(2*kp+1)*Nsrc + n]);
}

// ---------------- zero hmean ----------------
__global__ void zeroh_kernel(float* __restrict__ p)
{
    p[blockIdx.x*256 + threadIdx.x] = 0.f;
}

// ---------------- embedding: 16 rows/block, W staged in smem ----------------
__global__ void embed_kernel(const float* __restrict__ x, const float* __restrict__ W,
                             const float* __restrict__ bb, __half* __restrict__ h)
{
    __shared__ float Ws[Din*Dd];
    __shared__ float xs[16*Din];
    __shared__ float bsm[Dd];
    const int tid = threadIdx.x;
    const int m0 = blockIdx.x*16;
#pragma unroll
    for (int i = tid; i < Din*Dd; i += 256) Ws[i] = W[i];
    xs[tid] = x[m0*Din + tid];
    bsm[tid] = bb[tid];
    __syncthreads();
    const int d = tid;
#pragma unroll
    for (int r = 0; r < 16; r++) {
        float a = bsm[d];
#pragma unroll
        for (int k = 0; k < Din; k++) a = fmaf(xs[r*Din + k], Ws[k*Dd + d], a);
        h[(size_t)(m0+r)*Dd + d] = __float2half(a);
    }
}

// ---------------- FP16 GEMM (128x128 tile): pair-wise cp.async, ldmatrix A, u64 B ----------------
#define AST 20
#define B2ST 132
#define A_SZ (128*AST)
#define B_SZ (8*B2ST*2)
#define TG_SMEM (4*(A_SZ + B_SZ)*4)   // 74752 bytes

template<int RELU>
__global__ __launch_bounds__(256, 2) void tgemm_kernel(
    const uint32_t* __restrict__ A, const uint32_t* __restrict__ Wp,
    const float* __restrict__ bias, uint32_t* __restrict__ C,
    int M, int Nd, int Kd)
{
    const int Kd2 = Kd >> 1, Nd2 = Nd >> 1;
    extern __shared__ uint32_t dsm[];
    uint32_t* Asm = dsm;
    uint32_t* Bsm = dsm + 4*A_SZ;

    const int tid = threadIdx.x;
    const int warp = tid >> 5;
    const int lane = tid & 31;
    const int bm = blockIdx.y, bn = blockIdx.x;
    const int wm = warp & 3;
    const int wn = warp >> 2;
    const int qid = lane >> 2;
    const int tig = lane & 3;

    const int a_r0 = tid >> 1, a_c0 = (tid & 1) << 3;
    const int b_r = tid >> 5, b_c = tid & 31;

    const int row_sel = (lane & 7) + ((lane >> 3) & 1) * 8;
    const int col_sel = (lane >> 4) * 4;
    const uint32_t a_lm_off = (uint32_t)(((wm*32 + row_sel)*AST + col_sel) * 4);
    const uint32_t asm_base = (uint32_t)__cvta_generic_to_shared(Asm);

    const uint32_t* Ap = A + (size_t)(bm*128)*Kd2;
    const uint64_t* Bp = (const uint64_t*)Wp + (size_t)bn*128;

    float acc[2][8][4];
#pragma unroll
    for (int mt = 0; mt < 2; mt++)
#pragma unroll
        for (int nt = 0; nt < 8; nt++)
#pragma unroll
            for (int i = 0; i < 4; i++) acc[mt][nt][i] = 0.f;

    const int niter = Kd >> 5;
    const int npair = niter >> 1;

#define LOAD_TILE(ck, s) do {                                                      \
        int _ck = (ck), _s = (s);                                                  \
        const uint32_t* Ap2 = Ap + _ck*16;                                         \
        const uint64_t* Bp2 = Bp + (size_t)(_ck*8 + b_r)*Nd;                       \
        cp16(&Asm[_s*A_SZ + a_r0*AST + a_c0],     Ap2 + (size_t)a_r0*Kd2 + a_c0);  \
        cp16(&Asm[_s*A_SZ + a_r0*AST + a_c0 + 4], Ap2 + (size_t)a_r0*Kd2 + a_c0 + 4); \
        cp16(&Bsm[_s*B_SZ + b_r*(2*B2ST) + b_c*4],       Bp2 + b_c*2);             \
        cp16(&Bsm[_s*B_SZ + b_r*(2*B2ST) + b_c*4 + 128], Bp2 + b_c*2 + 64);        \
    } while (0)

    LOAD_TILE(0, 0);
    LOAD_TILE(1, 1);
    CP_COMMIT();

    for (int p = 0; p < npair; p++) {
        CP_WAIT(0);
        __syncthreads();

        if (p + 1 < npair) {
            int sb = ((p + 1) & 1) << 1;
            LOAD_TILE(2*(p+1),     sb);
            LOAD_TILE(2*(p+1) + 1, sb + 1);
        }
        CP_COMMIT();

#pragma unroll
        for (int half = 0; half < 2; half++) {
            const int stg = ((p & 1) << 1) + half;
            const uint32_t stage_base = asm_base + (uint32_t)(stg*A_SZ)*4;
            const uint2* B2 = (const uint2*)(Bsm + stg*B_SZ);
#pragma unroll
            for (int ks = 0; ks < 2; ks++) {
                uint32_t afrag[2][4];
#pragma unroll
                for (int mt = 0; mt < 2; mt++)
                    ldmx4(afrag[mt], stage_base + a_lm_off + (uint32_t)((mt*16*AST + ks*8)*4));
#pragma unroll
                for (int nt = 0; nt < 8; nt++) {
                    int cn = wn*64 + nt*8 + qid;
                    uint2 bv = B2[(ks*4 + tig)*B2ST + cn];
                    uint32_t bfrag[2] = { bv.x, bv.y };
#pragma unroll
                    for (int mt = 0; mt < 2; mt++)
                        mma_f16(acc[mt][nt], afrag[mt], bfrag);
                }
            }
        }
    }
#undef LOAD_TILE

#pragma unroll
    for (int mt = 0; mt < 2; mt++) {
        int r0 = bm*128 + wm*32 + mt*16 + qid;
#pragma unroll
        for (int nt = 0; nt < 8; nt++) {
            int c0 = bn*128 + wn*64 + nt*8 + 2*tig;
            float b0 = bias ? bias[c0]   : 0.f;
            float b1 = bias ? bias[c0+1] : 0.f;
            float v0 = acc[mt][nt][0] + b0, v1 = acc[mt][nt][1] + b1;
            float v2 = acc[mt][nt][2] + b0, v3 = acc[mt][nt][3] + b1;
            if (RELU) {
                v0 = fmaxf(v0, 0.f); v1 = fmaxf(v1, 0.f);
                v2 = fmaxf(v2, 0.f); v3 = fmaxf(v3, 0.f);
            }
            int cu = c0 >> 1;
            C[(size_t)r0*Nd2 + cu]     = pkhf(v0, v1);
            C[(size_t)(r0+8)*Nd2 + cu] = pkhf(v2, v3);
        }
    }
}

// ---------------- fused GEMM (64x256 tile) + LN epilogue OR scores epilogue ----------------
#define ASTF 20
#define B2STF 260
#define A_SZF (64*ASTF)
#define B_SZF (8*B2STF*2)
#define TL_SMEM (4*(A_SZF + B_SZF)*4)   // 87040 bytes

template<int MODE>
__global__ __launch_bounds__(256, 2) void tgemm_ln_kernel(
    const uint32_t* __restrict__ A, const uint32_t* __restrict__ Wp,
    const float* __restrict__ bias, uint32_t* __restrict__ Hio,
    int Kd,
    const float* __restrict__ g, const float* __restrict__ bta,
    const float* __restrict__ qvv, float* __restrict__ sc)
{
    const int Kd2 = Kd >> 1;
    extern __shared__ uint32_t dsm[];
    uint32_t* Asm = dsm;
    uint32_t* Bsm = dsm + 4*A_SZF;

    const int tid = threadIdx.x;
    const int warp = tid >> 5;
    const int lane = tid & 31;
    const int bm = blockIdx.x;
    const int wm = warp & 1;
    const int wn = warp >> 1;
    const int qid = lane >> 2;
    const int tig = lane & 3;

    const int a_r0 = tid >> 2, a_c0 = (tid & 3) << 2;
    const int b_r = tid >> 5, b_c = tid & 31;

    const int row_sel = (lane & 7) + ((lane >> 3) & 1) * 8;
    const int col_sel = (lane >> 4) * 4;
    const uint32_t a_lm_off = (uint32_t)(((wm*32 + row_sel)*ASTF + col_sel) * 4);
    const uint32_t asm_base = (uint32_t)__cvta_generic_to_shared(Asm);

    const uint32_t* Ap = A + (size_t)(bm*64)*Kd2;
    const uint64_t* Bp = (const uint64_t*)Wp;

    float acc[2][8][4];
#pragma unroll
    for (int mt = 0; mt < 2; mt++)
#pragma unroll
        for (int nt = 0; nt < 8; nt++)
#pragma unroll
            for (int i = 0; i < 4; i++) acc[mt][nt][i] = 0.f;

    const int niter = Kd >> 5;
    const int npair = niter >> 1;

#define LOAD_TILEF(ck, s) do {                                                     \
        int _ck = (ck), _s = (s);                                                  \
        const uint32_t* Ap2 = Ap + _ck*16;                                         \
        const uint64_t* Bp2 = Bp + (size_t)(_ck*8 + b_r)*256;                      \
        cp16(&Asm[_s*A_SZF + a_r0*ASTF + a_c0], Ap2 + (size_t)a_r0*Kd2 + a_c0);    \
        _Pragma("unroll")                                                          \
        for (int _j = 0; _j < 4; _j++)                                             \
            cp16(&Bsm[_s*B_SZF + b_r*(2*B2STF) + (b_c + 32*_j)*4],                 \
                 Bp2 + (b_c + 32*_j)*2);                                           \
    } while (0)

    LOAD_TILEF(0, 0);
    LOAD_TILEF(1, 1);
    CP_COMMIT();

    for (int p = 0; p < npair; p++) {
        CP_WAIT(0);
        __syncthreads();

        if (p + 1 < npair) {
            int sb = ((p + 1) & 1) << 1;
            LOAD_TILEF(2*(p+1),     sb);
            LOAD_TILEF(2*(p+1) + 1, sb + 1);
        }
        CP_COMMIT();

#pragma unroll
        for (int half = 0; half < 2; half++) {
            const int stg = ((p & 1) << 1) + half;
            const uint32_t stage_base = asm_base + (uint32_t)(stg*A_SZF)*4;
            const uint2* B2 = (const uint2*)(Bsm + stg*B_SZF);
#pragma unroll
            for (int ks = 0; ks < 2; ks++) {
                uint32_t afrag[2][4];
#pragma unroll
                for (int mt = 0; mt < 2; mt++)
                    ldmx4(afrag[mt], stage_base + a_lm_off + (uint32_t)((mt*16*ASTF + ks*8)*4));
#pragma unroll
                for (int nt = 0; nt < 8; nt++) {
                    int cn = wn*64 + nt*8 + qid;
                    uint2 bv = B2[(ks*4 + tig)*B2STF + cn];
                    uint32_t bfrag[2] = { bv.x, bv.y };
#pragma unroll
                    for (int mt = 0; mt < 2; mt++)
                        mma_f16(acc[mt][nt], afrag[mt], bfrag);
                }
            }
        }
    }
#undef LOAD_TILEF

    __syncthreads();
    float2* Sf2 = (float2*)dsm;           // [64][132] float2
#pragma unroll
    for (int mt = 0; mt < 2; mt++) {
        int rl0 = wm*32 + mt*16 + qid;
#pragma unroll
        for (int nt = 0; nt < 8; nt++) {
            int cu = wn*32 + nt*4 + tig;
            float b0 = 0.f, b1 = 0.f;
            if (MODE == 0 && bias) { b0 = bias[2*cu]; b1 = bias[2*cu+1]; }
            float v0 = acc[mt][nt][0] + b0, v1 = acc[mt][nt][1] + b1;
            float v2 = acc[mt][nt][2] + b0, v3 = acc[mt][nt][3] + b1;
            if (MODE == 0) {
                uint32_t h0 = Hio[(size_t)(bm*64 + rl0)*128 + cu];
                uint32_t h1 = Hio[(size_t)(bm*64 + rl0 + 8)*128 + cu];
                __half2 hh0 = *(__half2*)&h0;
                __half2 hh1 = *(__half2*)&h1;
                v0 += __half2float(hh0.x); v1 += __half2float(hh0.y);
                v2 += __half2float(hh1.x); v3 += __half2float(hh1.y);
            }
            float2 p0; p0.x = v0; p0.y = v1;
            float2 p1; p1.x = v2; p1.y = v3;
            Sf2[rl0*132 + cu]       = p0;
            Sf2[(rl0 + 8)*132 + cu] = p1;
        }
    }
    __syncthreads();

    if (MODE == 0) {
#pragma unroll
        for (int r = 0; r < 8; r++) {
            int row = warp*8 + r;
            float v[8];
            float s = 0.f;
#pragma unroll
            for (int j = 0; j < 4; j++) {
                float2 t = Sf2[row*132 + lane + j*32];
                v[2*j] = t.x; v[2*j+1] = t.y;
                s += t.x + t.y;
            }
#pragma unroll
            for (int o = 16; o; o >>= 1) s += __shfl_xor_sync(0xffffffffu, s, o);
            float mean = s * (1.f/256.f);
            float vs = 0.f;
#pragma unroll
            for (int i = 0; i < 8; i++) { float d = v[i]-mean; vs = fmaf(d, d, vs); }
#pragma unroll
            for (int o = 16; o; o >>= 1) vs += __shfl_xor_sync(0xffffffffu, vs, o);
            float rstd = rsqrtf(vs * (1.f/256.f) + 1e-5f);
#pragma unroll
            for (int j = 0; j < 4; j++) {
                int c = 2*(lane + j*32);
                float o0 = (v[2*j]  -mean)*rstd*g[c]   + bta[c];
                float o1 = (v[2*j+1]-mean)*rstd*g[c+1] + bta[c+1];
                Hio[(size_t)(bm*64 + row)*128 + lane + j*32] = pkhf(o0, o1);
            }
        }
    } else {
        const int b = (bm*64) >> 10;
        const float* qrow = qvv + b*Dd;
#pragma unroll
        for (int r = 0; r < 8; r++) {
            int row = warp*8 + r;
            float s = 0.f;
#pragma unroll
            for (int j = 0; j < 4; j++) {
                float2 t = Sf2[row*132 + lane + j*32];
                int c = 2*(lane + j*32);
                s = fmaf(t.x, qrow[c], s);
                s = fmaf(t.y, qrow[c+1], s);
            }
#pragma unroll
            for (int o = 16; o; o >>= 1) s += __shfl_xor_sync(0xffffffffu, s, o);
            if (lane == 0) sc[bm*64 + row] = s * 0.0625f;
        }
    }
}

// ---------------- fp16 flash attention: cp.async double-buffered K + raw V ----------------
#define QKV_RS 384
#define O_RS   128
#define KST 36
#define VRS 32
#define VST 72
#define PST 36
#define K_SZ (64*KST)
#define VR_SZ (64*VRS)
#define ATT_SMEM ((2*K_SZ + 2*VR_SZ + 32*VST + 8*16*PST)*4)

__global__ void __launch_bounds__(256) attn_mma_kernel(
    const uint32_t* __restrict__ QKV, uint32_t* __restrict__ O)
{
    extern __shared__ uint32_t sm[];
    uint32_t* Kst  = sm;
    uint32_t* Vraw = sm + 2*K_SZ;
    uint32_t* Vs   = sm + 2*K_SZ + 2*VR_SZ;
    const int tid = threadIdx.x;
    const int warp = tid >> 5, lane = tid & 31;
    const int qid = lane >> 2, tig = lane & 3;
    uint32_t* Psw = sm + 2*K_SZ + 2*VR_SZ + 32*VST + warp*16*PST;

    const int qt = blockIdx.x, head = blockIdx.y, b = blockIdx.z;
    const size_t qbase = ((size_t)b*Nn)*QKV_RS + head*(DH/2);
    const size_t kbase = qbase + 128;
    const size_t vbase = qbase + 256;
    const size_t obase = ((size_t)b*Nn)*O_RS + head*(DH/2);
    const int q0 = qt*128 + warp*16;

    uint32_t qa[4][4];
#pragma unroll
    for (int s = 0; s < 4; s++) {
        qa[s][0] = QKV[qbase + (size_t)(q0+qid  )*QKV_RS + s*8 + tig];
        qa[s][1] = QKV[qbase + (size_t)(q0+qid+8)*QKV_RS + s*8 + tig];
        qa[s][2] = QKV[qbase + (size_t)(q0+qid  )*QKV_RS + s*8 + tig + 4];
        qa[s][3] = QKV[qbase + (size_t)(q0+qid+8)*QKV_RS + s*8 + tig + 4];
    }

    float oacc[8][4];
#pragma unroll
    for (int dn = 0; dn < 8; dn++)
#pragma unroll
        for (int i = 0; i < 4; i++) oacc[dn][i] = 0.f;
    float m0 = -1e30f, m1 = -1e30f, l0 = 0.f, l1 = 0.f;
    const float scale = 0.125f;

    const int kr = tid >> 3, kq = (tid & 7) << 2;
    const int vr = tid >> 2, vq = (tid & 3) << 3;
    const int np = tid >> 3, dq = tid & 7;

    cp16(&Kst[kr*KST + kq],       QKV + kbase + (size_t)kr*QKV_RS + kq);
    cp16(&Kst[(kr+32)*KST + kq],  QKV + kbase + (size_t)(kr+32)*QKV_RS + kq);
    cp16(&Vraw[vr*VRS + vq],      QKV + vbase + (size_t)vr*QKV_RS + vq);
    cp16(&Vraw[vr*VRS + vq + 4],  QKV + vbase + (size_t)vr*QKV_RS + vq + 4);
    CP_COMMIT();

    int buf = 0;
    const int ntile = Nn/64;
    for (int jt = 0; jt < ntile; jt++) {
        if (jt + 1 < ntile) {
            int j1 = (jt+1)*64, nb = buf ^ 1;
            cp16(&Kst[nb*K_SZ + kr*KST + kq],      QKV + kbase + (size_t)(j1+kr)*QKV_RS + kq);
            cp16(&Kst[nb*K_SZ + (kr+32)*KST + kq], QKV + kbase + (size_t)(j1+kr+32)*QKV_RS + kq);
            cp16(&Vraw[nb*VR_SZ + vr*VRS + vq],    QKV + vbase + (size_t)(j1+vr)*QKV_RS + vq);
            cp16(&Vraw[nb*VR_SZ + vr*VRS + vq+4],  QKV + vbase + (size_t)(j1+vr)*QKV_RS + vq+4);
        }
        CP_COMMIT();
        CP_WAIT(1);
        __syncthreads();

        const uint32_t* Ks = &Kst[buf*K_SZ];
        const uint32_t* Vr = &Vraw[buf*VR_SZ];

        {
            uint4 r0 = *(const uint4*)(Vr + (2*np  )*VRS + dq*4);
            uint4 r1 = *(const uint4*)(Vr + (2*np+1)*VRS + dq*4);
            uint4 o0, o1;
            o0.x = __byte_perm(r0.x, r1.x, 0x5410); o0.y = __byte_perm(r0.x, r1.x, 0x7632);
            o0.z = __byte_perm(r0.y, r1.y, 0x5410); o0.w = __byte_perm(r0.y, r1.y, 0x7632);
            o1.x = __byte_perm(r0.z, r1.z, 0x5410); o1.y = __byte_perm(r0.z, r1.z, 0x7632);
            o1.z = __byte_perm(r0.w, r1.w, 0x5410); o1.w = __byte_perm(r0.w, r1.w, 0x7632);
            *(uint4*)&Vs[np*VST + dq*8]     = o0;
            *(uint4*)&Vs[np*VST + dq*8 + 4] = o1;
        }

        float sacc[8][4];
#pragma unroll
        for (int nt = 0; nt < 8; nt++)
#pragma unroll
            for (int i = 0; i < 4; i++) sacc[nt][i] = 0.f;
#pragma unroll
        for (int s = 0; s < 4; s++) {
#pragma unroll
            for (int nt = 0; nt < 8; nt++) {
                uint32_t bfrag[2];
                bfrag[0] = Ks[(nt*8+qid)*KST + s*8 + tig];
                bfrag[1] = Ks[(nt*8+qid)*KST + s*8 + tig + 4];
                mma_f16(sacc[nt], qa[s], bfrag);
            }
        }
#pragma unroll
        for (int nt = 0; nt < 8; nt++)
#pragma unroll
            for (int i = 0; i < 4; i++) sacc[nt][i] *= scale;

        float tm0 = -1e30f, tm1 = -1e30f;
#pragma unroll
        for (int nt = 0; nt < 8; nt++) {
            tm0 = fmaxf(tm0, fmaxf(sacc[nt][0], sacc[nt][1]));
            tm1 = fmaxf(tm1, fmaxf(sacc[nt][2], sacc[nt][3]));
        }
        tm0 = fmaxf(tm0, __shfl_xor_sync(0xffffffffu, tm0, 1));
        tm0 = fmaxf(tm0, __shfl_xor_sync(0xffffffffu, tm0, 2));
        tm1 = fmaxf(tm1, __shfl_xor_sync(0xffffffffu, tm1, 1));
        tm1 = fmaxf(tm1, __shfl_xor_sync(0xffffffffu, tm1, 2));
        float mn0 = fmaxf(m0, tm0), mn1 = fmaxf(m1, tm1);
        float c0 = __expf(m0 - mn0), c1 = __expf(m1 - mn1);
        m0 = mn0; m1 = mn1;
        l0 *= c0; l1 *= c1;
#pragma unroll
        for (int dn = 0; dn < 8; dn++) {
            oacc[dn][0] *= c0; oacc[dn][1] *= c0;
            oacc[dn][2] *= c1; oacc[dn][3] *= c1;
        }
#pragma unroll
        for (int nt = 0; nt < 8; nt++) {
            float p0 = __expf(sacc[nt][0] - m0);
            float p1 = __expf(sacc[nt][1] - m0);
            float p2 = __expf(sacc[nt][2] - m1);
            float p3 = __expf(sacc[nt][3] - m1);
            l0 += p0 + p1; l1 += p2 + p3;
            Psw[qid*PST     + nt*4 + tig] = pkhf(p0, p1);
            Psw[(qid+8)*PST + nt*4 + tig] = pkhf(p2, p3);
        }
        __syncthreads();

#pragma unroll
        for (int sj = 0; sj < 4; sj++) {
            uint32_t afrag[4];
            afrag[0] = Psw[qid*PST     + sj*8 + tig];
            afrag[1] = Psw[(qid+8)*PST + sj*8 + tig];
            afrag[2] = Psw[qid*PST     + sj*8 + tig + 4];
            afrag[3] = Psw[(qid+8)*PST + sj*8 + tig + 4];
#pragma unroll
            for (int dn = 0; dn < 8; dn++) {
                uint32_t bfrag[2];
                bfrag[0] = Vs[(sj*8+tig  )*VST + dn*8 + qid];
                bfrag[1] = Vs[(sj*8+tig+4)*VST + dn*8 + qid];
                mma_f16(oacc[dn], afrag, bfrag);
            }
        }
        buf ^= 1;
    }

    l0 += __shfl_xor_sync(0xffffffffu, l0, 1);
    l0 += __shfl_xor_sync(0xffffffffu, l0, 2);
    l1 += __shfl_xor_sync(0xffffffffu, l1, 1);
    l1 += __shfl_xor_sync(0xffffffffu, l1, 2);
    float inv0 = 1.f / l0, inv1 = 1.f / l1;
#pragma unroll
    for (int dn = 0; dn < 8; dn++) {
        int cu = dn*4 + tig;
        O[obase + (size_t)(q0+qid  )*O_RS + cu] = pkhf(oacc[dn][0]*inv0, oacc[dn][1]*inv0);
        O[obase + (size_t)(q0+qid+8)*O_RS + cu] = pkhf(oacc[dn][2]*inv1, oacc[dn][3]*inv1);
    }
}

// ---------------- h_mean: 4 partial blocks per batch + atomics ----------------
__global__ void hmean_kernel(const __half* __restrict__ h, float* __restrict__ hm)
{
    int b = blockIdx.y, seg = blockIdx.x;
    int d = threadIdx.x;
    const __half* p = h + ((size_t)b*Nn + seg*256)*Dd + d;
    float s = 0.f;
#pragma unroll 16
    for (int n = 0; n < 256; n++) s += __half2float(p[(size_t)n*Dd]);
    atomicAdd(&hm[b*Dd + d], s * (1.f/1024.f));
}

// ---------------- small row GEMM (fp32), column-chunked grid ----------------
template<int RELU>
__global__ void rowgemm_kernel(const float* __restrict__ A, const float* __restrict__ W,
                               const float* __restrict__ bias, float* __restrict__ C,
                               int Kd, int Nd)
{
    int b = blockIdx.y;
    int nch = gridDim.x;
    int c0 = blockIdx.x * (Nd / nch);
    int c1 = c0 + (Nd / nch);
    __shared__ float xs[1024];
    for (int i = threadIdx.x; i < Kd; i += blockDim.x) xs[i] = A[(size_t)b*Kd + i];
    __syncthreads();
    for (int d = c0 + threadIdx.x; d < c1; d += blockDim.x) {
        float acc = bias ? bias[d] : 0.f;
        for (int k = 0; k < Kd; k++) acc = fmaf(xs[k], W[(size_t)k*Nd + d], acc);
        if (RELU) acc = fmaxf(acc, 0.f);
        C[(size_t)b*Nd + d] = acc;
    }
}

// ---------------- finale: softmaxes + fast top-64 + sel ----------------
__global__ void finale_kernel(const float* __restrict__ scores, const float* __restrict__ gumbel,
                              const float* __restrict__ logits,
                              float* __restrict__ out_w, float* __restrict__ out_idx,
                              float* __restrict__ out_sel)
{
    int b = blockIdx.x, tid = threadIdx.x;
    const int wid = tid >> 5, lane = tid & 31;
    __shared__ float w[1024];
    __shared__ float al[1024];
    __shared__ float red[256];
    __shared__ unsigned long long kred[8];
    __shared__ int selidx[64];

    float lm = -1e30f;
    for (int i = tid; i < 1024; i += 256) {
        float v = (scores[b*Nn+i] + gumbel[b*Nn+i]) * 2.0f;
        w[i] = v; lm = fmaxf(lm, v);
    }
    red[tid] = lm; __syncthreads();
    for (int s = 128; s; s >>= 1) { if (tid < s) red[tid] = fmaxf(red[tid], red[tid+s]); __syncthreads(); }
    float M = red[0]; __syncthreads();
    float ls = 0.f;
    for (int i = tid; i < 1024; i += 256) { float e = __expf(w[i]-M); w[i] = e; ls += e; }
    red[tid] = ls; __syncthreads();
    for (int s = 128; s; s >>= 1) { if (tid < s) red[tid] += red[tid+s]; __syncthreads(); }
    float invS = 1.f / red[0]; __syncthreads();
    for (int i = tid; i < 1024; i += 256) {
        float wi = w[i]*invS; w[i] = wi; out_w[b*Nn+i] = wi;
    }

    lm = -1e30f;
    for (int i = tid; i < 1024; i += 256) { float v = logits[b*Nn+i]; al[i] = v; lm = fmaxf(lm, v); }
    __syncthreads();
    red[tid] = lm; __syncthreads();
    for (int s = 128; s; s >>= 1) { if (tid < s) red[tid] = fmaxf(red[tid], red[tid+s]); __syncthreads(); }
    M = red[0]; __syncthreads();
    ls = 0.f;
    for (int i = tid; i < 1024; i += 256) { float e = __expf(al[i]-M); al[i] = e; ls += e; }
    red[tid] = ls; __syncthreads();
    for (int s = 128; s; s >>= 1) { if (tid < s) red[tid] += red[tid+s]; __syncthreads(); }
    invS = 1.f / red[0]; __syncthreads();
    for (int i = tid; i < 1024; i += 256) al[i] *= invS;
    __syncthreads();

    for (int kk = 0; kk < 64; kk++) {
        unsigned long long best = 0ull;
#pragma unroll
        for (int t = 0; t < 4; t++) {
            int i = tid + t*256;
            float v = w[i];
            unsigned long long key = (v < 0.f) ? 0ull
                : (((unsigned long long)__float_as_uint(v)) << 32) | (unsigned long long)(1023 - i);
            best = (key > best) ? key : best;
        }
#pragma unroll
        for (int o = 16; o; o >>= 1) {
            unsigned long long ot = __shfl_xor_sync(0xffffffffu, best, o);
            best = (ot > best) ? ot : best;
        }
        if (lane == 0) kred[wid] = best;
        __syncthreads();
        if (tid == 0) {
            unsigned long long bb2 = kred[0];
#pragma unroll
            for (int j = 1; j < 8; j++) if (kred[j] > bb2) bb2 = kred[j];
            int idx = 1023 - (int)(bb2 & 0x3FFull);
            selidx[kk] = idx;
            w[idx] = -1.0f;
        }
        __syncthreads();
    }

    float sv = 0.f;
    if (tid < 64) sv = al[selidx[tid]];
    red[tid] = (tid < 64) ? sv : 0.f; __syncthreads();
    for (int s = 128; s; s >>= 1) { if (tid < s) red[tid] += red[tid+s]; __syncthreads(); }
    float inv = 1.f / (red[0] + 1e-12f);
    if (tid < 64) {
        out_idx[b*64 + tid] = (float)selidx[tid];
        out_sel[b*64 + tid] = sv * inv;
    }
}

// ---------------- launch ----------------
extern "C" void kernel_launch(void* const* d_in, const int* in_sizes, int n_in,
                              void* d_out, int out_size)
{
    const float* x       = (const float*)d_in[0];
    const float* gumbel  = (const float*)d_in[1];
    const float* emb_W   = (const float*)d_in[2];
    const float* emb_b   = (const float*)d_in[3];
    const float* Wq      = (const float*)d_in[4];
    const float* Wk      = (const float*)d_in[5];
    const float* Wv      = (const float*)d_in[6];
    const float* Wo      = (const float*)d_in[7];
    const float* ln1_g   = (const float*)d_in[8];
    const float* ln1_b   = (const float*)d_in[9];
    const float* ln2_g   = (const float*)d_in[10];
    const float* ln2_b   = (const float*)d_in[11];
    const float* ffn_W1  = (const float*)d_in[12];
    const float* ffn_b1  = (const float*)d_in[13];
    const float* ffn_W2  = (const float*)d_in[14];
    const float* ffn_b2  = (const float*)d_in[15];
    const float* sha_Wq  = (const float*)d_in[16];
    const float* sha_Wk  = (const float*)d_in[17];
    const float* alloc_W1= (const float*)d_in[18];
    const float* alloc_b1= (const float*)d_in[19];
    const float* alloc_W2= (const float*)d_in[20];
    const float* alloc_b2= (const float*)d_in[21];

    __half *h, *scr;
    uint32_t* wpk;
    float *hmean, *qv, *t1, *logits, *scores;
    cudaGetSymbolAddress((void**)&h,      g_h);
    cudaGetSymbolAddress((void**)&scr,    g_scr);
    cudaGetSymbolAddress((void**)&wpk,    g_wpk);
    cudaGetSymbolAddress((void**)&hmean,  g_hmean);
    cudaGetSymbolAddress((void**)&qv,     g_qv);
    cudaGetSymbolAddress((void**)&t1,     g_t1);
    cudaGetSymbolAddress((void**)&logits, g_logits);
    cudaGetSymbolAddress((void**)&scores, g_scores);

    static int cfg_done = 0;
    if (!cfg_done) {
        cudaFuncSetAttribute(tgemm_kernel<0>,
                             cudaFuncAttributeMaxDynamicSharedMemorySize, TG_SMEM);
        cudaFuncSetAttribute(tgemm_kernel<1>,
                             cudaFuncAttributeMaxDynamicSharedMemorySize, TG_SMEM);
        cudaFuncSetAttribute(tgemm_ln_kernel<0>,
                             cudaFuncAttributeMaxDynamicSharedMemorySize, TL_SMEM);
        cudaFuncSetAttribute(tgemm_ln_kernel<1>,
                             cudaFuncAttributeMaxDynamicSharedMemorySize, TL_SMEM);
        cudaFuncSetAttribute(attn_mma_kernel,
                             cudaFuncAttributeMaxDynamicSharedMemorySize, ATT_SMEM);
        cfg_done = 1;
    }

    packall_kernel<<<dim3(1536, 7), 256>>>(Wq, Wk, Wv, Wo, ffn_W1, ffn_W2, sha_Wk, wpk);
    zeroh_kernel<<<Bb*Dd/256, 256>>>(hmean);

    __half* qkv = scr;                          // [M][768]
    __half* ao  = scr + (size_t)MM*768;         // [M][256]

    embed_kernel<<<MM/16, 256>>>(x, emb_W, emb_b, h);

    const dim3 gQKV(768/128, MM/128);  // (6,512)
    const dim3 gF1(DFF/128, MM/128);   // (8,512)

    for (int i = 0; i < Ll; i++) {
        tgemm_kernel<0><<<gQKV, 256, TG_SMEM>>>((const uint32_t*)h, wpk + OFF_QKV + (size_t)i*128*768, nullptr, (uint32_t*)qkv, MM, 768, Dd);
        attn_mma_kernel<<<dim3(Nn/128, Hh, Bb), 256, ATT_SMEM>>>((const uint32_t*)qkv, (uint32_t*)ao);
        tgemm_ln_kernel<0><<<MM/64, 256, TL_SMEM>>>(
            (const uint32_t*)ao, wpk + OFF_WO + (size_t)i*128*256, nullptr, (uint32_t*)h,
            Dd, ln1_g + i*Dd, ln1_b + i*Dd, nullptr, nullptr);
        tgemm_kernel<1><<<gF1, 256, TG_SMEM>>>((const uint32_t*)h, wpk + OFF_W1 + (size_t)i*128*1024, ffn_b1 + i*DFF, (uint32_t*)scr, MM, DFF, Dd);
        tgemm_ln_kernel<0><<<MM/64, 256, TL_SMEM>>>(
            (const uint32_t*)scr, wpk + OFF_W2 + (size_t)i*512*256, ffn_b2 + i*Dd, (uint32_t*)h,
            DFF, ln2_g + i*Dd, ln2_b + i*Dd, nullptr, nullptr);
    }

    hmean_kernel<<<dim3(4, Bb), 256>>>(h, hmean);
    rowgemm_kernel<0><<<dim3(1, Bb), 256>>>(hmean, sha_Wq, nullptr, qv, Dd, Dd);
    tgemm_ln_kernel<1><<<MM/64, 256, TL_SMEM>>>(
        (const uint32_t*)h, wpk + OFF_SHA, nullptr, (uint32_t*)h,
        Dd, nullptr, nullptr, qv, scores);
    rowgemm_kernel<1><<<dim3(1, Bb), 256>>>(hmean, alloc_W1, alloc_b1, t1, Dd, Dd);
    rowgemm_kernel<0><<<dim3(4, Bb), 256>>>(t1, alloc_W2, alloc_b2, logits, Dd, Nn);

    float* out = (float*)d_out;
    finale_kernel<<<Bb, 256>>>(scores, gumbel, logits,
                               out,
                               out + Bb*Nn,
                               out + Bb*Nn + Bb*Kk);
}